// round 1
// baseline (speedup 1.0000x reference)
#include <cuda_runtime.h>
#include <cstdint>

#define HID 512
#define BATCH 512
#define IN_DIM 32
#define OUT_DIM 8
#define TF_DIM 24
#define SEQ 128
#define FUT 48
#define G4 2048          // 4*HID
#define K0T 544          // IN_DIM + HID  (also OUT_DIM + TF_DIM + HID)
#define K1T 1024         // HID + HID

#define BM 64
#define BN 128
#define BK 16
#define NTHREADS 256
#define AP 68            // padded A tile row length (even -> keeps 8B alignment)

// ---------------- persistent device scratch (no allocation allowed) -------------
__device__ float g_h0[2][BATCH * HID];
__device__ float g_c0[2][BATCH * HID];
__device__ float g_h1[2][BATCH * HID];
__device__ float g_c1[2][BATCH * HID];
__device__ float g_Wt0[K0T * G4];   // [k][4*j+g] gate-interleaved, transposed
__device__ float g_Wt1[K1T * G4];
__device__ float g_b0[G4];
__device__ float g_b1[G4];
__device__ float g_y[BATCH * OUT_DIM];

// ---------------- f32x2 packed math (sm_103a) ------------------------------------
__device__ __forceinline__ unsigned long long pack2(float lo, float hi) {
    unsigned long long r;
    asm("mov.b64 %0, {%1, %2};" : "=l"(r) : "f"(lo), "f"(hi));
    return r;
}
__device__ __forceinline__ void fma2(unsigned long long& acc,
                                     unsigned long long a,
                                     unsigned long long b) {
    asm("fma.rn.f32x2 %0, %1, %2, %0;" : "+l"(acc) : "l"(a), "l"(b));
}
__device__ __forceinline__ float2 unpack2(unsigned long long v) {
    float2 f;
    asm("mov.b64 {%0, %1}, %2;" : "=f"(f.x), "=f"(f.y) : "l"(v));
    return f;
}

__device__ __forceinline__ float sigf(float x) { return 1.0f / (1.0f + __expf(-x)); }

// ---------------- weight / bias / state prep -------------------------------------
__global__ void prep_w0(const float* __restrict__ w_ih, const float* __restrict__ w_hh) {
    int idx = blockIdx.x * blockDim.x + threadIdx.x;
    if (idx >= K0T * G4) return;
    int k = idx / G4, col = idx - k * G4;
    int j = col >> 2, g = col & 3;
    int row = g * HID + j;
    g_Wt0[idx] = (k < IN_DIM) ? w_ih[row * IN_DIM + k] : w_hh[row * HID + (k - IN_DIM)];
}

__global__ void prep_w1(const float* __restrict__ w_ih, const float* __restrict__ w_hh) {
    int idx = blockIdx.x * blockDim.x + threadIdx.x;
    if (idx >= K1T * G4) return;
    int k = idx / G4, col = idx - k * G4;
    int j = col >> 2, g = col & 3;
    int row = g * HID + j;
    g_Wt1[idx] = (k < HID) ? w_ih[row * HID + k] : w_hh[row * HID + (k - HID)];
}

__global__ void prep_bias(const float* __restrict__ bi0, const float* __restrict__ bh0,
                          const float* __restrict__ bi1, const float* __restrict__ bh1) {
    int col = blockIdx.x * blockDim.x + threadIdx.x;
    if (col >= G4) return;
    int j = col >> 2, g = col & 3;
    int row = g * HID + j;
    g_b0[col] = bi0[row] + bh0[row];
    g_b1[col] = bi1[row] + bh1[row];
}

__global__ void init_state(const float* __restrict__ h0in, const float* __restrict__ c0in) {
    int idx = blockIdx.x * blockDim.x + threadIdx.x;
    if (idx >= BATCH * HID) return;
    int j = idx & (HID - 1);
    g_h0[0][idx] = h0in[j];
    g_c0[0][idx] = c0in[j];
    g_h1[0][idx] = h0in[HID + j];
    g_c1[0][idx] = c0in[HID + j];
}

// ---------------- fused LSTM cell: GEMM + gate nonlinearity ----------------------
// gates[B, 4H] = concat(p1[B,k1], p2[B,k2], hprev[B,H]) @ Wt[Kt, 4H] + bias
// then c' = sig(f)*c + sig(i)*tanh(g);  h' = sig(o)*tanh(c')
__global__ __launch_bounds__(NTHREADS)
void lstm_cell(const float* __restrict__ p1, int k1,
               const float* __restrict__ p2, int k2,
               const float* __restrict__ hprev,
               const float* __restrict__ cprev,
               const float* __restrict__ Wt,
               const float* __restrict__ bias,
               int Kt,
               float* __restrict__ hout,
               float* __restrict__ cout) {
    __shared__ __align__(16) float As[BK][AP];
    __shared__ __align__(16) float Bs[BK][BN];

    const int tid = threadIdx.x;
    const int n0 = blockIdx.x * BN;   // gate-column offset
    const int m0 = blockIdx.y * BM;   // batch offset
    const int cg = tid & 31;          // hidden unit within block tile
    const int rg = tid >> 5;          // row group (warp id)
    const int k12 = k1 + k2;

    unsigned long long acc[4][4];     // [row-pair][gate], each packs 2 batch rows
#pragma unroll
    for (int i = 0; i < 4; ++i)
#pragma unroll
        for (int g = 0; g < 4; ++g) acc[i][g] = 0ull;

    const int ar = tid >> 2;          // A-load: row 0..63
    const int akq = (tid & 3) * 4;    // A-load: k base (4 consecutive k per thread)

    const int ntiles = Kt / BK;       // Kt is always a multiple of 16
    for (int t = 0; t < ntiles; ++t) {
        const int k0 = t * BK;
        // ---- load A tile (virtual concat) ----
        {
            const int gb = m0 + ar;
#pragma unroll
            for (int i = 0; i < 4; ++i) {
                int kk = akq + i;
                int gk = k0 + kk;
                float v;
                if (gk < k1)       v = p1[gb * k1 + gk];
                else if (gk < k12) v = p2[gb * k2 + (gk - k1)];
                else               v = hprev[gb * HID + (gk - k12)];
                As[kk][ar] = v;
            }
        }
        // ---- load B tile (coalesced float4) ----
        {
#pragma unroll
            for (int i = 0; i < 2; ++i) {
                int idx = tid + i * NTHREADS;
                int kk = idx >> 5;
                int c4 = (idx & 31) << 2;
                float4 v = *reinterpret_cast<const float4*>(
                    Wt + (size_t)(k0 + kk) * G4 + n0 + c4);
                *reinterpret_cast<float4*>(&Bs[kk][c4]) = v;
            }
        }
        __syncthreads();
        // ---- compute ----
#pragma unroll
        for (int kk = 0; kk < BK; ++kk) {
            float4 bv = *reinterpret_cast<const float4*>(&Bs[kk][cg << 2]);
            unsigned long long bb0 = pack2(bv.x, bv.x);
            unsigned long long bb1 = pack2(bv.y, bv.y);
            unsigned long long bb2 = pack2(bv.z, bv.z);
            unsigned long long bb3 = pack2(bv.w, bv.w);
#pragma unroll
            for (int rp = 0; rp < 4; ++rp) {
                unsigned long long aa = *reinterpret_cast<const unsigned long long*>(
                    &As[kk][rg * 8 + rp * 2]);
                fma2(acc[rp][0], aa, bb0);
                fma2(acc[rp][1], aa, bb1);
                fma2(acc[rp][2], aa, bb2);
                fma2(acc[rp][3], aa, bb3);
            }
        }
        __syncthreads();
    }

    // ---- epilogue: LSTM nonlinearity, write h', c' ----
    const int j = (n0 >> 2) + cg;
    const float bi = bias[n0 + (cg << 2) + 0];
    const float bf = bias[n0 + (cg << 2) + 1];
    const float bg = bias[n0 + (cg << 2) + 2];
    const float bo = bias[n0 + (cg << 2) + 3];
#pragma unroll
    for (int rp = 0; rp < 4; ++rp) {
        float2 vi = unpack2(acc[rp][0]);
        float2 vf = unpack2(acc[rp][1]);
        float2 vg = unpack2(acc[rp][2]);
        float2 vo = unpack2(acc[rp][3]);
#pragma unroll
        for (int h2 = 0; h2 < 2; ++h2) {
            int b = m0 + rg * 8 + rp * 2 + h2;
            float gi = (h2 ? vi.y : vi.x) + bi;
            float gf = (h2 ? vf.y : vf.x) + bf;
            float gg = (h2 ? vg.y : vg.x) + bg;
            float go = (h2 ? vo.y : vo.x) + bo;
            float cp = cprev[b * HID + j];
            float cn = sigf(gf) * cp + sigf(gi) * tanhf(gg);
            float hn = sigf(go) * tanhf(cn);
            hout[b * HID + j] = hn;
            cout[b * HID + j] = cn;
        }
    }
}

// ---------------- FC head: y = h1 @ fc_w^T + fc_b --------------------------------
__global__ void fc_kernel(const float* __restrict__ h1, const float* __restrict__ fcw,
                          const float* __restrict__ fcb, float* __restrict__ outp) {
    int idx = blockIdx.x * blockDim.x + threadIdx.x;   // 4096 = B * OUT
    int b = idx >> 3, o = idx & 7;
    const float* hr = h1 + b * HID;
    const float* wr = fcw + o * HID;
    float s = 0.0f;
#pragma unroll 8
    for (int jj = 0; jj < HID; ++jj) s += hr[jj] * wr[jj];
    s += fcb[o];
    g_y[idx] = s;
    outp[idx] = s;
}

// ---------------- host orchestration ---------------------------------------------
extern "C" void kernel_launch(void* const* d_in, const int* in_sizes, int n_in,
                              void* d_out, int out_size) {
    const float* x     = (const float*)d_in[0];
    const float* ft    = (const float*)d_in[1];
    const float* h0in  = (const float*)d_in[2];
    const float* c0in  = (const float*)d_in[3];
    const float* w_ih0 = (const float*)d_in[4];
    const float* w_hh0 = (const float*)d_in[5];
    const float* b_ih0 = (const float*)d_in[6];
    const float* b_hh0 = (const float*)d_in[7];
    const float* w_ih1 = (const float*)d_in[8];
    const float* w_hh1 = (const float*)d_in[9];
    const float* b_ih1 = (const float*)d_in[10];
    const float* b_hh1 = (const float*)d_in[11];
    const float* fcw   = (const float*)d_in[12];
    const float* fcb   = (const float*)d_in[13];
    float* out = (float*)d_out;

    float *h0p, *c0p, *h1p, *c1p, *wt0, *wt1, *b0p, *b1p, *yp;
    cudaGetSymbolAddress((void**)&h0p, g_h0);
    cudaGetSymbolAddress((void**)&c0p, g_c0);
    cudaGetSymbolAddress((void**)&h1p, g_h1);
    cudaGetSymbolAddress((void**)&c1p, g_c1);
    cudaGetSymbolAddress((void**)&wt0, g_Wt0);
    cudaGetSymbolAddress((void**)&wt1, g_Wt1);
    cudaGetSymbolAddress((void**)&b0p, g_b0);
    cudaGetSymbolAddress((void**)&b1p, g_b1);
    cudaGetSymbolAddress((void**)&yp,  g_y);

    prep_w0<<<(K0T * G4 + 255) / 256, 256>>>(w_ih0, w_hh0);
    prep_w1<<<(K1T * G4 + 255) / 256, 256>>>(w_ih1, w_hh1);
    prep_bias<<<(G4 + 255) / 256, 256>>>(b_ih0, b_hh0, b_ih1, b_hh1);
    init_state<<<(BATCH * HID + 255) / 256, 256>>>(h0in, c0in);

    const dim3 grid(G4 / BN, BATCH / BM);
    const int SN = BATCH * HID;
    int p = 0;

    // encoder
    for (int t = 0; t < SEQ; ++t) {
        lstm_cell<<<grid, NTHREADS>>>(x + (size_t)t * BATCH * IN_DIM, IN_DIM,
                                      nullptr, 0,
                                      h0p + p * SN, c0p + p * SN,
                                      wt0, b0p, K0T,
                                      h0p + (p ^ 1) * SN, c0p + (p ^ 1) * SN);
        lstm_cell<<<grid, NTHREADS>>>(h0p + (p ^ 1) * SN, HID,
                                      nullptr, 0,
                                      h1p + p * SN, c1p + p * SN,
                                      wt1, b1p, K1T,
                                      h1p + (p ^ 1) * SN, c1p + (p ^ 1) * SN);
        p ^= 1;
    }
    fc_kernel<<<16, 256>>>(h1p + p * SN, fcw, fcb, out);

    // autoregressive decode
    for (int t = 0; t < FUT - 1; ++t) {
        lstm_cell<<<grid, NTHREADS>>>(yp, OUT_DIM,
                                      ft + (size_t)t * BATCH * TF_DIM, TF_DIM,
                                      h0p + p * SN, c0p + p * SN,
                                      wt0, b0p, K0T,
                                      h0p + (p ^ 1) * SN, c0p + (p ^ 1) * SN);
        lstm_cell<<<grid, NTHREADS>>>(h0p + (p ^ 1) * SN, HID,
                                      nullptr, 0,
                                      h1p + p * SN, c1p + p * SN,
                                      wt1, b1p, K1T,
                                      h1p + (p ^ 1) * SN, c1p + (p ^ 1) * SN);
        p ^= 1;
        fc_kernel<<<16, 256>>>(h1p + p * SN, fcw, fcb,
                               out + (size_t)(t + 1) * BATCH * OUT_DIM);
    }
}

// round 2
// speedup vs baseline: 1.0010x; 1.0010x over previous
#include <cuda_runtime.h>
#include <cstdint>

#define HID 512
#define BATCH 512
#define IN_DIM 32
#define OUT_DIM 8
#define TF_DIM 24
#define SEQ 128
#define FUT 48
#define G4 2048          // 4*HID
#define K0T 544          // IN_DIM + HID  (also OUT_DIM + TF_DIM + HID)
#define K1T 1024         // HID + HID

#define BM 64
#define BN 128
#define BK 16
#define NTHREADS 256
#define AP 68            // padded A tile row length (even -> keeps 8B alignment)

// ---------------- persistent device scratch (no allocation allowed) -------------
__device__ float g_h0[2][BATCH * HID];
__device__ float g_c0[2][BATCH * HID];
__device__ float g_h1[2][BATCH * HID];
__device__ float g_c1[2][BATCH * HID];
__device__ float g_Wt0[K0T * G4];   // [k][4*j+g] gate-interleaved, transposed
__device__ float g_Wt1[K1T * G4];
__device__ float g_b0[G4];
__device__ float g_b1[G4];
__device__ float g_y[BATCH * OUT_DIM];

// ---------------- f32x2 packed math (sm_103a) ------------------------------------
__device__ __forceinline__ unsigned long long pack2(float lo, float hi) {
    unsigned long long r;
    asm("mov.b64 %0, {%1, %2};" : "=l"(r) : "f"(lo), "f"(hi));
    return r;
}
__device__ __forceinline__ void fma2(unsigned long long& acc,
                                     unsigned long long a,
                                     unsigned long long b) {
    asm("fma.rn.f32x2 %0, %1, %2, %0;" : "+l"(acc) : "l"(a), "l"(b));
}
__device__ __forceinline__ float2 unpack2(unsigned long long v) {
    float2 f;
    asm("mov.b64 {%0, %1}, %2;" : "=f"(f.x), "=f"(f.y) : "l"(v));
    return f;
}

__device__ __forceinline__ float sigf(float x) { return 1.0f / (1.0f + __expf(-x)); }

// ---------------- weight / bias / state prep -------------------------------------
__global__ void prep_w0(const float* __restrict__ w_ih, const float* __restrict__ w_hh) {
    int idx = blockIdx.x * blockDim.x + threadIdx.x;
    if (idx >= K0T * G4) return;
    int k = idx / G4, col = idx - k * G4;
    int j = col >> 2, g = col & 3;
    int row = g * HID + j;
    g_Wt0[idx] = (k < IN_DIM) ? w_ih[row * IN_DIM + k] : w_hh[row * HID + (k - IN_DIM)];
}

__global__ void prep_w1(const float* __restrict__ w_ih, const float* __restrict__ w_hh) {
    int idx = blockIdx.x * blockDim.x + threadIdx.x;
    if (idx >= K1T * G4) return;
    int k = idx / G4, col = idx - k * G4;
    int j = col >> 2, g = col & 3;
    int row = g * HID + j;
    g_Wt1[idx] = (k < HID) ? w_ih[row * HID + k] : w_hh[row * HID + (k - HID)];
}

__global__ void prep_bias(const float* __restrict__ bi0, const float* __restrict__ bh0,
                          const float* __restrict__ bi1, const float* __restrict__ bh1) {
    int col = blockIdx.x * blockDim.x + threadIdx.x;
    if (col >= G4) return;
    int j = col >> 2, g = col & 3;
    int row = g * HID + j;
    g_b0[col] = bi0[row] + bh0[row];
    g_b1[col] = bi1[row] + bh1[row];
}

__global__ void init_state(const float* __restrict__ h0in, const float* __restrict__ c0in) {
    int idx = blockIdx.x * blockDim.x + threadIdx.x;
    if (idx >= BATCH * HID) return;
    int j = idx & (HID - 1);
    g_h0[0][idx] = h0in[j];
    g_c0[0][idx] = c0in[j];
    g_h1[0][idx] = h0in[HID + j];
    g_c1[0][idx] = c0in[HID + j];
}

// ---------------- fused LSTM cell: GEMM + gate nonlinearity ----------------------
// gates[B, 4H] = concat(p1[B,k1], p2[B,k2], hprev[B,H]) @ Wt[Kt, 4H] + bias
// then c' = sig(f)*c + sig(i)*tanh(g);  h' = sig(o)*tanh(c')
__global__ __launch_bounds__(NTHREADS)
void lstm_cell(const float* __restrict__ p1, int k1,
               const float* __restrict__ p2, int k2,
               const float* __restrict__ hprev,
               const float* __restrict__ cprev,
               const float* __restrict__ Wt,
               const float* __restrict__ bias,
               int Kt,
               float* __restrict__ hout,
               float* __restrict__ cout) {
    __shared__ __align__(16) float As[BK][AP];
    __shared__ __align__(16) float Bs[BK][BN];

    const int tid = threadIdx.x;
    const int n0 = blockIdx.x * BN;   // gate-column offset
    const int m0 = blockIdx.y * BM;   // batch offset
    const int cg = tid & 31;          // hidden unit within block tile
    const int rg = tid >> 5;          // row group (warp id)
    const int k12 = k1 + k2;

    unsigned long long acc[4][4];     // [row-pair][gate], each packs 2 batch rows
#pragma unroll
    for (int i = 0; i < 4; ++i)
#pragma unroll
        for (int g = 0; g < 4; ++g) acc[i][g] = 0ull;

    const int ar = tid >> 2;          // A-load: row 0..63
    const int akq = (tid & 3) * 4;    // A-load: k base (4 consecutive k per thread)

    const int ntiles = Kt / BK;       // Kt is always a multiple of 16
    for (int t = 0; t < ntiles; ++t) {
        const int k0 = t * BK;
        // ---- load A tile (virtual concat) ----
        {
            const int gb = m0 + ar;
#pragma unroll
            for (int i = 0; i < 4; ++i) {
                int kk = akq + i;
                int gk = k0 + kk;
                float v;
                if (gk < k1)       v = p1[gb * k1 + gk];
                else if (gk < k12) v = p2[gb * k2 + (gk - k1)];
                else               v = hprev[gb * HID + (gk - k12)];
                As[kk][ar] = v;
            }
        }
        // ---- load B tile (coalesced float4) ----
        {
#pragma unroll
            for (int i = 0; i < 2; ++i) {
                int idx = tid + i * NTHREADS;
                int kk = idx >> 5;
                int c4 = (idx & 31) << 2;
                float4 v = *reinterpret_cast<const float4*>(
                    Wt + (size_t)(k0 + kk) * G4 + n0 + c4);
                *reinterpret_cast<float4*>(&Bs[kk][c4]) = v;
            }
        }
        __syncthreads();
        // ---- compute ----
#pragma unroll
        for (int kk = 0; kk < BK; ++kk) {
            float4 bv = *reinterpret_cast<const float4*>(&Bs[kk][cg << 2]);
            unsigned long long bb0 = pack2(bv.x, bv.x);
            unsigned long long bb1 = pack2(bv.y, bv.y);
            unsigned long long bb2 = pack2(bv.z, bv.z);
            unsigned long long bb3 = pack2(bv.w, bv.w);
#pragma unroll
            for (int rp = 0; rp < 4; ++rp) {
                unsigned long long aa = *reinterpret_cast<const unsigned long long*>(
                    &As[kk][rg * 8 + rp * 2]);
                fma2(acc[rp][0], aa, bb0);
                fma2(acc[rp][1], aa, bb1);
                fma2(acc[rp][2], aa, bb2);
                fma2(acc[rp][3], aa, bb3);
            }
        }
        __syncthreads();
    }

    // ---- epilogue: LSTM nonlinearity, write h', c' ----
    const int j = (n0 >> 2) + cg;
    const float bi = bias[n0 + (cg << 2) + 0];
    const float bf = bias[n0 + (cg << 2) + 1];
    const float bg = bias[n0 + (cg << 2) + 2];
    const float bo = bias[n0 + (cg << 2) + 3];
#pragma unroll
    for (int rp = 0; rp < 4; ++rp) {
        float2 vi = unpack2(acc[rp][0]);
        float2 vf = unpack2(acc[rp][1]);
        float2 vg = unpack2(acc[rp][2]);
        float2 vo = unpack2(acc[rp][3]);
#pragma unroll
        for (int h2 = 0; h2 < 2; ++h2) {
            int b = m0 + rg * 8 + rp * 2 + h2;
            float gi = (h2 ? vi.y : vi.x) + bi;
            float gf = (h2 ? vf.y : vf.x) + bf;
            float gg = (h2 ? vg.y : vg.x) + bg;
            float go = (h2 ? vo.y : vo.x) + bo;
            float cp = cprev[b * HID + j];
            float cn = sigf(gf) * cp + sigf(gi) * tanhf(gg);
            float hn = sigf(go) * tanhf(cn);
            hout[b * HID + j] = hn;
            cout[b * HID + j] = cn;
        }
    }
}

// ---------------- FC head: y = h1 @ fc_w^T + fc_b --------------------------------
__global__ void fc_kernel(const float* __restrict__ h1, const float* __restrict__ fcw,
                          const float* __restrict__ fcb, float* __restrict__ outp) {
    int idx = blockIdx.x * blockDim.x + threadIdx.x;   // 4096 = B * OUT
    int b = idx >> 3, o = idx & 7;
    const float* hr = h1 + b * HID;
    const float* wr = fcw + o * HID;
    float s = 0.0f;
#pragma unroll 8
    for (int jj = 0; jj < HID; ++jj) s += hr[jj] * wr[jj];
    s += fcb[o];
    g_y[idx] = s;
    outp[idx] = s;
}

// ---------------- host orchestration ---------------------------------------------
extern "C" void kernel_launch(void* const* d_in, const int* in_sizes, int n_in,
                              void* d_out, int out_size) {
    const float* x     = (const float*)d_in[0];
    const float* ft    = (const float*)d_in[1];
    const float* h0in  = (const float*)d_in[2];
    const float* c0in  = (const float*)d_in[3];
    const float* w_ih0 = (const float*)d_in[4];
    const float* w_hh0 = (const float*)d_in[5];
    const float* b_ih0 = (const float*)d_in[6];
    const float* b_hh0 = (const float*)d_in[7];
    const float* w_ih1 = (const float*)d_in[8];
    const float* w_hh1 = (const float*)d_in[9];
    const float* b_ih1 = (const float*)d_in[10];
    const float* b_hh1 = (const float*)d_in[11];
    const float* fcw   = (const float*)d_in[12];
    const float* fcb   = (const float*)d_in[13];
    float* out = (float*)d_out;

    float *h0p, *c0p, *h1p, *c1p, *wt0, *wt1, *b0p, *b1p, *yp;
    cudaGetSymbolAddress((void**)&h0p, g_h0);
    cudaGetSymbolAddress((void**)&c0p, g_c0);
    cudaGetSymbolAddress((void**)&h1p, g_h1);
    cudaGetSymbolAddress((void**)&c1p, g_c1);
    cudaGetSymbolAddress((void**)&wt0, g_Wt0);
    cudaGetSymbolAddress((void**)&wt1, g_Wt1);
    cudaGetSymbolAddress((void**)&b0p, g_b0);
    cudaGetSymbolAddress((void**)&b1p, g_b1);
    cudaGetSymbolAddress((void**)&yp,  g_y);

    prep_w0<<<(K0T * G4 + 255) / 256, 256>>>(w_ih0, w_hh0);
    prep_w1<<<(K1T * G4 + 255) / 256, 256>>>(w_ih1, w_hh1);
    prep_bias<<<(G4 + 255) / 256, 256>>>(b_ih0, b_hh0, b_ih1, b_hh1);
    init_state<<<(BATCH * HID + 255) / 256, 256>>>(h0in, c0in);

    const dim3 grid(G4 / BN, BATCH / BM);
    const int SN = BATCH * HID;
    int p = 0;

    // encoder
    for (int t = 0; t < SEQ; ++t) {
        lstm_cell<<<grid, NTHREADS>>>(x + (size_t)t * BATCH * IN_DIM, IN_DIM,
                                      nullptr, 0,
                                      h0p + p * SN, c0p + p * SN,
                                      wt0, b0p, K0T,
                                      h0p + (p ^ 1) * SN, c0p + (p ^ 1) * SN);
        lstm_cell<<<grid, NTHREADS>>>(h0p + (p ^ 1) * SN, HID,
                                      nullptr, 0,
                                      h1p + p * SN, c1p + p * SN,
                                      wt1, b1p, K1T,
                                      h1p + (p ^ 1) * SN, c1p + (p ^ 1) * SN);
        p ^= 1;
    }
    fc_kernel<<<16, 256>>>(h1p + p * SN, fcw, fcb, out);

    // autoregressive decode
    for (int t = 0; t < FUT - 1; ++t) {
        lstm_cell<<<grid, NTHREADS>>>(yp, OUT_DIM,
                                      ft + (size_t)t * BATCH * TF_DIM, TF_DIM,
                                      h0p + p * SN, c0p + p * SN,
                                      wt0, b0p, K0T,
                                      h0p + (p ^ 1) * SN, c0p + (p ^ 1) * SN);
        lstm_cell<<<grid, NTHREADS>>>(h0p + (p ^ 1) * SN, HID,
                                      nullptr, 0,
                                      h1p + p * SN, c1p + p * SN,
                                      wt1, b1p, K1T,
                                      h1p + (p ^ 1) * SN, c1p + (p ^ 1) * SN);
        p ^= 1;
        fc_kernel<<<16, 256>>>(h1p + p * SN, fcw, fcb,
                               out + (size_t)(t + 1) * BATCH * OUT_DIM);
    }
}

// round 4
// speedup vs baseline: 1.3640x; 1.3627x over previous
#include <cuda_runtime.h>
#include <cuda_bf16.h>
#include <cstdint>

#define HID 512
#define BATCH 512
#define G4 2048
#define KTOT0 576          // 64 (padded input slab) + 512 (h_prev)
#define KTOT1 1024         // 512 (h0 out) + 512 (h1 prev)
#define NCH0 9
#define NCH1 16
#define SEQ 128
#define FUT 48
#define TF_DIM 24
#define OUT_DIM 8

#define CELL_THREADS 256
#define APITCH 144                    // 64 bf16 + 8 pad  (16B aligned, bank-staggered)
#define A_SPLIT_B (64 * APITCH)       // 9216
#define B_OFF (2 * A_SPLIT_B)         // 18432
#define B_SPLIT_B (128 * APITCH)      // 18432
#define STAGE_B (B_OFF + 2 * B_SPLIT_B)   // 55296
#define SMEM_B (2 * STAGE_B)              // 110592

// ---------------- persistent device buffers ----------------
__device__ __align__(256) __nv_bfloat16 g_w0hi[G4 * KTOT0];
__device__ __align__(256) __nv_bfloat16 g_w0lo[G4 * KTOT0];
__device__ __align__(256) __nv_bfloat16 g_w1hi[G4 * KTOT1];
__device__ __align__(256) __nv_bfloat16 g_w1lo[G4 * KTOT1];
__device__ __align__(256) __nv_bfloat16 g_xph[SEQ * BATCH * 64];
__device__ __align__(256) __nv_bfloat16 g_xpl[SEQ * BATCH * 64];
__device__ __align__(256) __nv_bfloat16 g_iph[BATCH * 64];
__device__ __align__(256) __nv_bfloat16 g_ipl[BATCH * 64];
__device__ __align__(256) __nv_bfloat16 g_h0h[2][BATCH * HID];
__device__ __align__(256) __nv_bfloat16 g_h0l[2][BATCH * HID];
__device__ __align__(256) __nv_bfloat16 g_h1h[2][BATCH * HID];
__device__ __align__(256) __nv_bfloat16 g_h1l[2][BATCH * HID];
__device__ __align__(256) float g_c0[BATCH * HID];
__device__ __align__(256) float g_c1[BATCH * HID];
__device__ __align__(256) float g_b0[G4];
__device__ __align__(256) float g_b1[G4];

// ---------------- PTX helpers (all base sm_103-legal) ----------------
__device__ __forceinline__ uint32_t smem_u32(const void* p) {
    uint32_t a;
    asm("{ .reg .u64 t; cvta.to.shared.u64 t, %1; cvt.u32.u64 %0, t; }" : "=r"(a) : "l"(p));
    return a;
}
__device__ __forceinline__ void cp16(uint32_t dst, const void* src) {
    asm volatile("cp.async.cg.shared.global [%0], [%1], 16;" :: "r"(dst), "l"(src) : "memory");
}
#define CP_COMMIT() asm volatile("cp.async.commit_group;" ::: "memory")
#define CP_WAIT1()  asm volatile("cp.async.wait_group 1;" ::: "memory")
#define CP_WAIT0()  asm volatile("cp.async.wait_group 0;" ::: "memory")

__device__ __forceinline__ void ldsm4(uint32_t* r, uint32_t addr) {
    asm volatile("ldmatrix.sync.aligned.m8n8.x4.shared.b16 {%0,%1,%2,%3}, [%4];"
                 : "=r"(r[0]), "=r"(r[1]), "=r"(r[2]), "=r"(r[3]) : "r"(addr));
}
__device__ __forceinline__ void mma16816(float* c, const uint32_t* a, const uint32_t* b) {
    asm volatile(
        "mma.sync.aligned.m16n8k16.row.col.f32.bf16.bf16.f32 "
        "{%0,%1,%2,%3}, {%4,%5,%6,%7}, {%8,%9}, {%0,%1,%2,%3};"
        : "+f"(c[0]), "+f"(c[1]), "+f"(c[2]), "+f"(c[3])
        : "r"(a[0]), "r"(a[1]), "r"(a[2]), "r"(a[3]), "r"(b[0]), "r"(b[1]));
}

__device__ __forceinline__ void splitbf(float v, __nv_bfloat16& hi, __nv_bfloat16& lo) {
    hi = __float2bfloat16(v);
    lo = __float2bfloat16(v - __bfloat162float(hi));
}
__device__ __forceinline__ float sigf(float x) { return 1.0f / (1.0f + __expf(-x)); }

// ---------------- prep kernels ----------------
__global__ void prep_w0(const float* __restrict__ wih, const float* __restrict__ whh) {
    int idx = blockIdx.x * blockDim.x + threadIdx.x;
    if (idx >= G4 * KTOT0) return;
    int n = idx / KTOT0, k = idx - n * KTOT0;
    int row = (n & 3) * HID + (n >> 2);
    float v;
    if (k < 64) v = (k < 32) ? wih[row * 32 + k] : 0.0f;
    else        v = whh[row * HID + (k - 64)];
    splitbf(v, g_w0hi[idx], g_w0lo[idx]);
}
__global__ void prep_w1(const float* __restrict__ wih, const float* __restrict__ whh) {
    int idx = blockIdx.x * blockDim.x + threadIdx.x;
    if (idx >= G4 * KTOT1) return;
    int n = idx >> 10, k = idx & 1023;
    int row = (n & 3) * HID + (n >> 2);
    float v = (k < HID) ? wih[row * HID + k] : whh[row * HID + (k - HID)];
    splitbf(v, g_w1hi[idx], g_w1lo[idx]);
}
__global__ void prep_bias(const float* __restrict__ bi0, const float* __restrict__ bh0,
                          const float* __restrict__ bi1, const float* __restrict__ bh1) {
    int n = blockIdx.x * blockDim.x + threadIdx.x;
    if (n >= G4) return;
    int row = (n & 3) * HID + (n >> 2);
    g_b0[n] = bi0[row] + bh0[row];
    g_b1[n] = bi1[row] + bh1[row];
}
__global__ void prep_xpad(const float* __restrict__ x) {
    int idx = blockIdx.x * blockDim.x + threadIdx.x;
    if (idx >= SEQ * BATCH * 64) return;
    int k = idx & 63, bt = idx >> 6;
    float v = (k < 32) ? x[bt * 32 + k] : 0.0f;
    splitbf(v, g_xph[idx], g_xpl[idx]);
}
__global__ void prep_ipzero() {
    int idx = blockIdx.x * blockDim.x + threadIdx.x;
    if (idx >= BATCH * 32) return;
    int b = idx >> 5, i = idx & 31;
    g_iph[b * 64 + 32 + i] = __float2bfloat16(0.0f);
    g_ipl[b * 64 + 32 + i] = __float2bfloat16(0.0f);
}
__global__ void init_state(const float* __restrict__ h0in, const float* __restrict__ c0in) {
    int idx = blockIdx.x * blockDim.x + threadIdx.x;
    if (idx >= BATCH * HID) return;
    int j = idx & (HID - 1);
    splitbf(h0in[j], g_h0h[0][idx], g_h0l[0][idx]);
    splitbf(h0in[HID + j], g_h1h[0][idx], g_h1l[0][idx]);
    g_c0[idx] = c0in[j];
    g_c1[idx] = c0in[HID + j];
}

// ---------------- chunk loader ----------------
// A source for chunk c: virtual concat of (optional 64-wide slab a0) then a1 (h), then a2 (h).
__device__ __forceinline__ void load_chunk(
    uint32_t stage, int tid, int c, int m0, int n0,
    const __nv_bfloat16* a0hi, const __nv_bfloat16* a0lo,
    const __nv_bfloat16* a1hi, const __nv_bfloat16* a1lo,
    const __nv_bfloat16* a2hi, const __nv_bfloat16* a2lo,
    const __nv_bfloat16* whi, const __nv_bfloat16* wlo, int ktot)
{
    const char *sAh, *sAl;
    size_t pitchA;
    if (a0hi != nullptr && c == 0) {
        sAh = (const char*)a0hi + (size_t)m0 * 128;
        sAl = (const char*)a0lo + (size_t)m0 * 128;
        pitchA = 128;
    } else {
        int s1 = c - (a0hi != nullptr ? 1 : 0);
        const __nv_bfloat16 *hi, *lo;
        if (s1 < 8) { hi = a1hi; lo = a1lo; } else { hi = a2hi; lo = a2lo; s1 -= 8; }
        sAh = (const char*)hi + (size_t)m0 * 1024 + (size_t)s1 * 128;
        sAl = (const char*)lo + (size_t)m0 * 1024 + (size_t)s1 * 128;
        pitchA = 1024;
    }
    const char* sBh = (const char*)whi + ((size_t)n0 * ktot + (size_t)c * 64) * 2;
    const char* sBl = (const char*)wlo + ((size_t)n0 * ktot + (size_t)c * 64) * 2;
    const size_t pitchB = (size_t)ktot * 2;

    // A: 1024 16B-transfers (2 splits x 64 rows x 8 chunks)
#pragma unroll
    for (int i = 0; i < 4; ++i) {
        int idx = tid * 4 + i;
        int split = idx >> 9, rem = idx & 511;
        int r = rem >> 3, q = rem & 7;
        uint32_t dst = stage + split * A_SPLIT_B + r * APITCH + q * 16;
        const char* src = (split ? sAl : sAh) + (size_t)r * pitchA + q * 16;
        cp16(dst, src);
    }
    // B: 2048 16B-transfers (2 splits x 128 rows x 8 chunks)
#pragma unroll
    for (int i = 0; i < 8; ++i) {
        int idx = tid * 8 + i;
        int split = idx >> 10, rem = idx & 1023;
        int r = rem >> 3, q = rem & 7;
        uint32_t dst = stage + B_OFF + split * B_SPLIT_B + r * APITCH + q * 16;
        const char* src = (split ? sBl : sBh) + (size_t)r * pitchB + q * 16;
        cp16(dst, src);
    }
}

// ---------------- fused LSTM cell (mma.sync split-bf16) ----------------
__global__ __launch_bounds__(CELL_THREADS, 1)
void lstm_cell_mma(const __nv_bfloat16* a0hi, const __nv_bfloat16* a0lo,
                   const __nv_bfloat16* a1hi, const __nv_bfloat16* a1lo,
                   const __nv_bfloat16* a2hi, const __nv_bfloat16* a2lo,
                   const __nv_bfloat16* whi, const __nv_bfloat16* wlo,
                   int ktot, int nch,
                   const float* __restrict__ bias,
                   float* __restrict__ cbuf,
                   __nv_bfloat16* __restrict__ hOutHi,
                   __nv_bfloat16* __restrict__ hOutLo)
{
    extern __shared__ char smem_raw[];
    const uint32_t sb = smem_u32(smem_raw);

    const int tid = threadIdx.x;
    const int l = tid & 31;
    const int w = tid >> 5;
    const int wm = w & 1;          // 0..1 : 32-row slab
    const int wn = w >> 1;         // 0..3 : 32-col slab
    const int n0 = blockIdx.x * 128;
    const int m0 = blockIdx.y * 64;

    float acc[2][4][4];
#pragma unroll
    for (int mt = 0; mt < 2; ++mt)
#pragma unroll
        for (int nt = 0; nt < 4; ++nt)
#pragma unroll
            for (int i = 0; i < 4; ++i) acc[mt][nt][i] = 0.0f;

    load_chunk(sb, tid, 0, m0, n0, a0hi, a0lo, a1hi, a1lo, a2hi, a2lo, whi, wlo, ktot);
    CP_COMMIT();

    // precomputed ldmatrix intra-tile offsets
    const uint32_t aRow = (uint32_t)(wm * 32 + (l & 15));           // + mt*16
    const uint32_t aColB = (uint32_t)((l >> 4) * 16);               // bytes, + k0*2
    const uint32_t bRow = (uint32_t)(wn * 32 + (l & 7) + ((l >> 4) & 1) * 8); // + ntp*16
    const uint32_t bColB = (uint32_t)(((l >> 3) & 1) * 16);         // bytes, + k0*2

    for (int c = 0; c < nch; ++c) {
        const uint32_t stage = sb + (uint32_t)(c & 1) * STAGE_B;
        if (c + 1 < nch) {
            load_chunk(sb + (uint32_t)((c + 1) & 1) * STAGE_B, tid, c + 1, m0, n0,
                       a0hi, a0lo, a1hi, a1lo, a2hi, a2lo, whi, wlo, ktot);
            CP_COMMIT();
            CP_WAIT1();
        } else {
            CP_WAIT0();
        }
        __syncthreads();

#pragma unroll
        for (int ks = 0; ks < 4; ++ks) {
            const uint32_t kb = (uint32_t)(ks * 32);   // k0*2 bytes
            uint32_t a[2][2][4];
#pragma unroll
            for (int split = 0; split < 2; ++split)
#pragma unroll
                for (int mt = 0; mt < 2; ++mt) {
                    uint32_t addr = stage + split * A_SPLIT_B +
                                    (aRow + mt * 16) * APITCH + aColB + kb;
                    ldsm4(a[split][mt], addr);
                }
            uint32_t b[2][4][2];
#pragma unroll
            for (int split = 0; split < 2; ++split)
#pragma unroll
                for (int ntp = 0; ntp < 2; ++ntp) {
                    uint32_t r4[4];
                    uint32_t addr = stage + B_OFF + split * B_SPLIT_B +
                                    (bRow + ntp * 16) * APITCH + bColB + kb;
                    ldsm4(r4, addr);
                    b[split][ntp * 2][0] = r4[0]; b[split][ntp * 2][1] = r4[1];
                    b[split][ntp * 2 + 1][0] = r4[2]; b[split][ntp * 2 + 1][1] = r4[3];
                }
#pragma unroll
            for (int mt = 0; mt < 2; ++mt)
#pragma unroll
                for (int nt = 0; nt < 4; ++nt) {
                    mma16816(acc[mt][nt], a[0][mt], b[0][nt]);  // hi*hi
                    mma16816(acc[mt][nt], a[0][mt], b[1][nt]);  // hi*lo
                    mma16816(acc[mt][nt], a[1][mt], b[0][nt]);  // lo*hi
                }
        }
        __syncthreads();
    }

    // ---- epilogue: assemble gates via lane-pair exchange, LSTM update ----
    const bool odd = (l & 1) != 0;
#pragma unroll
    for (int mt = 0; mt < 2; ++mt)
#pragma unroll
        for (int nt = 0; nt < 4; ++nt) {
            float* cc = acc[mt][nt];
            // even lane holds (i,f) for rows r,r+8 ; odd lane holds (g,o)
            float send1 = odd ? cc[0] : cc[2];
            float send2 = odd ? cc[1] : cc[3];
            float r1 = __shfl_xor_sync(0xffffffffu, send1, 1);
            float r2 = __shfl_xor_sync(0xffffffffu, send2, 1);
            float gi, gf, gg, go;
            if (!odd) { gi = cc[0]; gf = cc[1]; gg = r1; go = r2; }
            else      { gi = r1;    gf = r2;    gg = cc[2]; go = cc[3]; }

            const int j = ((n0 + wn * 32 + nt * 8) >> 2) + ((l & 3) >> 1);
            const float4 b4 = *(const float4*)(bias + 4 * j);
            gi += b4.x; gf += b4.y; gg += b4.z; go += b4.w;

            const int bglob = m0 + wm * 32 + mt * 16 + (l >> 2) + (odd ? 8 : 0);
            const int ix = bglob * HID + j;
            float cp = cbuf[ix];
            float cn = sigf(gf) * cp + sigf(gi) * tanhf(gg);
            float hn = sigf(go) * tanhf(cn);
            cbuf[ix] = cn;
            __nv_bfloat16 hi, lo;
            splitbf(hn, hi, lo);
            hOutHi[ix] = hi;
            hOutLo[ix] = lo;
        }
}

// ---------------- FC head (+ next decode-input packing) ----------------
__global__ void fc_tc(const __nv_bfloat16* __restrict__ h1hi,
                      const __nv_bfloat16* __restrict__ h1lo,
                      const float* __restrict__ fcw, const float* __restrict__ fcb,
                      float* __restrict__ outp, const float* __restrict__ tf) {
    int idx = blockIdx.x * blockDim.x + threadIdx.x;   // 4096 = B*OUT
    int b = idx >> 3, o = idx & 7;
    const __nv_bfloat16* hh = h1hi + b * HID;
    const __nv_bfloat16* hl = h1lo + b * HID;
    const float* wr = fcw + o * HID;
    float s = fcb[o];
#pragma unroll 8
    for (int j = 0; j < HID; ++j)
        s += (__bfloat162float(hh[j]) + __bfloat162float(hl[j])) * wr[j];
    outp[b * OUT_DIM + o] = s;
    if (tf != nullptr) {
        splitbf(s, g_iph[b * 64 + o], g_ipl[b * 64 + o]);
#pragma unroll
        for (int m = 0; m < 3; ++m) {
            float v = tf[b * TF_DIM + o * 3 + m];
            splitbf(v, g_iph[b * 64 + 8 + o * 3 + m], g_ipl[b * 64 + 8 + o * 3 + m]);
        }
    }
}

// ---------------- host orchestration ----------------
extern "C" void kernel_launch(void* const* d_in, const int* in_sizes, int n_in,
                              void* d_out, int out_size) {
    const float* x     = (const float*)d_in[0];
    const float* ft    = (const float*)d_in[1];
    const float* h0in  = (const float*)d_in[2];
    const float* c0in  = (const float*)d_in[3];
    const float* w_ih0 = (const float*)d_in[4];
    const float* w_hh0 = (const float*)d_in[5];
    const float* b_ih0 = (const float*)d_in[6];
    const float* b_hh0 = (const float*)d_in[7];
    const float* w_ih1 = (const float*)d_in[8];
    const float* w_hh1 = (const float*)d_in[9];
    const float* b_ih1 = (const float*)d_in[10];
    const float* b_hh1 = (const float*)d_in[11];
    const float* fcw   = (const float*)d_in[12];
    const float* fcb   = (const float*)d_in[13];
    float* out = (float*)d_out;

    cudaFuncSetAttribute(lstm_cell_mma, cudaFuncAttributeMaxDynamicSharedMemorySize,
                         SMEM_B);

    __nv_bfloat16 *w0h, *w0l, *w1h, *w1l, *xph, *xpl, *iph, *ipl;
    __nv_bfloat16 *h0h, *h0l, *h1h, *h1l;
    float *c0p, *c1p, *b0p, *b1p;
    cudaGetSymbolAddress((void**)&w0h, g_w0hi); cudaGetSymbolAddress((void**)&w0l, g_w0lo);
    cudaGetSymbolAddress((void**)&w1h, g_w1hi); cudaGetSymbolAddress((void**)&w1l, g_w1lo);
    cudaGetSymbolAddress((void**)&xph, g_xph);  cudaGetSymbolAddress((void**)&xpl, g_xpl);
    cudaGetSymbolAddress((void**)&iph, g_iph);  cudaGetSymbolAddress((void**)&ipl, g_ipl);
    cudaGetSymbolAddress((void**)&h0h, g_h0h);  cudaGetSymbolAddress((void**)&h0l, g_h0l);
    cudaGetSymbolAddress((void**)&h1h, g_h1h);  cudaGetSymbolAddress((void**)&h1l, g_h1l);
    cudaGetSymbolAddress((void**)&c0p, g_c0);   cudaGetSymbolAddress((void**)&c1p, g_c1);
    cudaGetSymbolAddress((void**)&b0p, g_b0);   cudaGetSymbolAddress((void**)&b1p, g_b1);

    prep_w0<<<(G4 * KTOT0 + 255) / 256, 256>>>(w_ih0, w_hh0);
    prep_w1<<<(G4 * KTOT1 + 255) / 256, 256>>>(w_ih1, w_hh1);
    prep_bias<<<(G4 + 255) / 256, 256>>>(b_ih0, b_hh0, b_ih1, b_hh1);
    prep_xpad<<<(SEQ * BATCH * 64 + 255) / 256, 256>>>(x);
    prep_ipzero<<<(BATCH * 32 + 255) / 256, 256>>>();
    init_state<<<(BATCH * HID + 255) / 256, 256>>>(h0in, c0in);

    const dim3 grid(16, 8);
    const int SN = BATCH * HID;
    int p = 0;

    // encoder
    for (int t = 0; t < SEQ; ++t) {
        lstm_cell_mma<<<grid, CELL_THREADS, SMEM_B>>>(
            xph + (size_t)t * BATCH * 64, xpl + (size_t)t * BATCH * 64,
            h0h + p * SN, h0l + p * SN, nullptr, nullptr,
            w0h, w0l, KTOT0, NCH0, b0p, c0p,
            h0h + (p ^ 1) * SN, h0l + (p ^ 1) * SN);
        lstm_cell_mma<<<grid, CELL_THREADS, SMEM_B>>>(
            nullptr, nullptr,
            h0h + (p ^ 1) * SN, h0l + (p ^ 1) * SN,
            h1h + p * SN, h1l + p * SN,
            w1h, w1l, KTOT1, NCH1, b1p, c1p,
            h1h + (p ^ 1) * SN, h1l + (p ^ 1) * SN);
        p ^= 1;
    }
    fc_tc<<<16, 256>>>(h1h + p * SN, h1l + p * SN, fcw, fcb, out, ft);

    // autoregressive decode
    for (int t = 0; t < FUT - 1; ++t) {
        lstm_cell_mma<<<grid, CELL_THREADS, SMEM_B>>>(
            iph, ipl,
            h0h + p * SN, h0l + p * SN, nullptr, nullptr,
            w0h, w0l, KTOT0, NCH0, b0p, c0p,
            h0h + (p ^ 1) * SN, h0l + (p ^ 1) * SN);
        lstm_cell_mma<<<grid, CELL_THREADS, SMEM_B>>>(
            nullptr, nullptr,
            h0h + (p ^ 1) * SN, h0l + (p ^ 1) * SN,
            h1h + p * SN, h1l + p * SN,
            w1h, w1l, KTOT1, NCH1, b1p, c1p,
            h1h + (p ^ 1) * SN, h1l + (p ^ 1) * SN);
        p ^= 1;
        fc_tc<<<16, 256>>>(h1h + p * SN, h1l + p * SN, fcw, fcb,
                           out + (size_t)(t + 1) * BATCH * OUT_DIM,
                           (t + 1 < FUT - 1) ? (ft + (size_t)(t + 1) * BATCH * TF_DIM)
                                             : nullptr);
    }
}

// round 5
// speedup vs baseline: 2.0962x; 1.5368x over previous
#include <cuda_runtime.h>
#include <cuda_fp16.h>
#include <cstdint>

#define HID 512
#define BATCH 512
#define G4 2048
#define KTOT0 576          // 64 (padded input slab) + 512 (h_prev)
#define KTOT1 1024         // 512 (h0 out) + 512 (h1 prev)
#define NCH0 9
#define NCH1 16
#define SEQ 128
#define FUT 48
#define TF_DIM 24
#define OUT_DIM 8

#define CELL_THREADS 512
#define APITCH 144                    // 64 fp16 (128B) + 16B pad, bank-staggered
#define A_BYTES (64 * APITCH)         // 9216
#define B_OFF A_BYTES
#define B_SPLIT_B (128 * APITCH)      // 18432
#define STAGE_B (B_OFF + 2 * B_SPLIT_B)   // 46080
#define SMEM_B (2 * STAGE_B)              // 92160
#define LO_SCALE 1024.0f
#define LO_INV 0.0009765625f

// ---------------- persistent device buffers ----------------
__device__ __align__(256) __half g_w0h[G4 * KTOT0];
__device__ __align__(256) __half g_w0l[G4 * KTOT0];   // (w - hi) * 1024
__device__ __align__(256) __half g_w1h[G4 * KTOT1];
__device__ __align__(256) __half g_w1l[G4 * KTOT1];
__device__ __align__(256) __half g_xp[SEQ * BATCH * 64];
__device__ __align__(256) __half g_ip[BATCH * 64];
__device__ __align__(256) __half g_h0[2][BATCH * HID];
__device__ __align__(256) __half g_h1[2][BATCH * HID];
__device__ __align__(256) float g_h1f[BATCH * HID];   // fp32 h1 for exact FC
__device__ __align__(256) float g_c0[BATCH * HID];
__device__ __align__(256) float g_c1[BATCH * HID];
__device__ __align__(256) float g_b0[G4];
__device__ __align__(256) float g_b1[G4];

// ---------------- PTX helpers (base sm_103-legal only) ----------------
__device__ __forceinline__ uint32_t smem_u32(const void* p) {
    uint32_t a;
    asm("{ .reg .u64 t; cvta.to.shared.u64 t, %1; cvt.u32.u64 %0, t; }" : "=r"(a) : "l"(p));
    return a;
}
__device__ __forceinline__ void cp16(uint32_t dst, const void* src) {
    asm volatile("cp.async.cg.shared.global [%0], [%1], 16;" :: "r"(dst), "l"(src) : "memory");
}
#define CP_COMMIT() asm volatile("cp.async.commit_group;" ::: "memory")
#define CP_WAIT1()  asm volatile("cp.async.wait_group 1;" ::: "memory")
#define CP_WAIT0()  asm volatile("cp.async.wait_group 0;" ::: "memory")

__device__ __forceinline__ void ldsm4(uint32_t* r, uint32_t addr) {
    asm volatile("ldmatrix.sync.aligned.m8n8.x4.shared.b16 {%0,%1,%2,%3}, [%4];"
                 : "=r"(r[0]), "=r"(r[1]), "=r"(r[2]), "=r"(r[3]) : "r"(addr));
}
__device__ __forceinline__ void mma16816(float* c, const uint32_t* a, const uint32_t* b) {
    asm volatile(
        "mma.sync.aligned.m16n8k16.row.col.f32.f16.f16.f32 "
        "{%0,%1,%2,%3}, {%4,%5,%6,%7}, {%8,%9}, {%0,%1,%2,%3};"
        : "+f"(c[0]), "+f"(c[1]), "+f"(c[2]), "+f"(c[3])
        : "r"(a[0]), "r"(a[1]), "r"(a[2]), "r"(a[3]), "r"(b[0]), "r"(b[1]));
}

__device__ __forceinline__ void splitw(float v, __half& hi, __half& lo) {
    hi = __float2half(v);
    lo = __float2half((v - __half2float(hi)) * LO_SCALE);
}
__device__ __forceinline__ float sigf(float x) { return 1.0f / (1.0f + __expf(-x)); }

// ---------------- prep kernels ----------------
__global__ void prep_w0(const float* __restrict__ wih, const float* __restrict__ whh) {
    int idx = blockIdx.x * blockDim.x + threadIdx.x;
    if (idx >= G4 * KTOT0) return;
    int n = idx / KTOT0, k = idx - n * KTOT0;
    int row = (n & 3) * HID + (n >> 2);
    float v;
    if (k < 64) v = (k < 32) ? wih[row * 32 + k] : 0.0f;
    else        v = whh[row * HID + (k - 64)];
    splitw(v, g_w0h[idx], g_w0l[idx]);
}
__global__ void prep_w1(const float* __restrict__ wih, const float* __restrict__ whh) {
    int idx = blockIdx.x * blockDim.x + threadIdx.x;
    if (idx >= G4 * KTOT1) return;
    int n = idx >> 10, k = idx & 1023;
    int row = (n & 3) * HID + (n >> 2);
    float v = (k < HID) ? wih[row * HID + k] : whh[row * HID + (k - HID)];
    splitw(v, g_w1h[idx], g_w1l[idx]);
}
__global__ void prep_bias(const float* __restrict__ bi0, const float* __restrict__ bh0,
                          const float* __restrict__ bi1, const float* __restrict__ bh1) {
    int n = blockIdx.x * blockDim.x + threadIdx.x;
    if (n >= G4) return;
    int row = (n & 3) * HID + (n >> 2);
    g_b0[n] = bi0[row] + bh0[row];
    g_b1[n] = bi1[row] + bh1[row];
}
__global__ void prep_xpad(const float* __restrict__ x) {
    int idx = blockIdx.x * blockDim.x + threadIdx.x;
    if (idx >= SEQ * BATCH * 64) return;
    int k = idx & 63, bt = idx >> 6;
    g_xp[idx] = __float2half((k < 32) ? x[bt * 32 + k] : 0.0f);
}
__global__ void prep_ipzero() {
    int idx = blockIdx.x * blockDim.x + threadIdx.x;
    if (idx >= BATCH * 32) return;
    int b = idx >> 5, i = idx & 31;
    g_ip[b * 64 + 32 + i] = __float2half(0.0f);
}
__global__ void init_state(const float* __restrict__ h0in, const float* __restrict__ c0in) {
    int idx = blockIdx.x * blockDim.x + threadIdx.x;
    if (idx >= BATCH * HID) return;
    int j = idx & (HID - 1);
    g_h0[0][idx] = __float2half(h0in[j]);
    g_h1[0][idx] = __float2half(h0in[HID + j]);
    g_c0[idx] = c0in[j];
    g_c1[idx] = c0in[HID + j];
}

// ---------------- chunk loader ----------------
__device__ __forceinline__ void load_chunk(
    uint32_t stage, int tid, int c, int m0, int n0,
    const __half* a0, const __half* a1, const __half* a2,
    const __half* wh, const __half* wl, int ktot)
{
    const char* sA;
    size_t pitchA;
    if (a0 != nullptr && c == 0) {
        sA = (const char*)a0 + (size_t)m0 * 128;
        pitchA = 128;
    } else {
        int s1 = c - (a0 != nullptr ? 1 : 0);
        const __half* src = (s1 < 8) ? a1 : a2;
        if (s1 >= 8) s1 -= 8;
        sA = (const char*)src + (size_t)m0 * 1024 + (size_t)s1 * 128;
        pitchA = 1024;
    }
    const char* sBh = (const char*)wh + ((size_t)n0 * ktot + (size_t)c * 64) * 2;
    const char* sBl = (const char*)wl + ((size_t)n0 * ktot + (size_t)c * 64) * 2;
    const size_t pitchB = (size_t)ktot * 2;

    // A: 512 x 16B (one per thread)
    {
        int r = tid >> 3, q = tid & 7;
        cp16(stage + r * APITCH + q * 16, sA + (size_t)r * pitchA + q * 16);
    }
    // B: 2048 x 16B (four per thread, warp-contiguous)
#pragma unroll
    for (int i = 0; i < 4; ++i) {
        int idx = tid + i * CELL_THREADS;
        int split = idx >> 10, rem = idx & 1023;
        int r = rem >> 3, q = rem & 7;
        cp16(stage + B_OFF + split * B_SPLIT_B + r * APITCH + q * 16,
             (split ? sBl : sBh) + (size_t)r * pitchB + q * 16);
    }
}

// ---------------- fused LSTM cell (mma.sync fp16, weight-split) ----------------
__global__ __launch_bounds__(CELL_THREADS, 1)
void lstm_cell_mma(const __half* a0, const __half* a1, const __half* a2,
                   const __half* wh, const __half* wl,
                   int ktot, int nch,
                   const float* __restrict__ bias,
                   float* __restrict__ cbuf,
                   __half* __restrict__ hOut,
                   float* __restrict__ hOutF)
{
    extern __shared__ char smem_raw[];
    const uint32_t sb = smem_u32(smem_raw);

    const int tid = threadIdx.x;
    const int l = tid & 31;
    const int w = tid >> 5;
    const int wm = w & 3;          // 0..3 : 16-row slab
    const int wn = w >> 2;         // 0..3 : 32-col slab
    const int n0 = blockIdx.x * 128;
    const int m0 = blockIdx.y * 64;

    float acc1[4][4], acc2[4][4];
#pragma unroll
    for (int nt = 0; nt < 4; ++nt)
#pragma unroll
        for (int i = 0; i < 4; ++i) { acc1[nt][i] = 0.0f; acc2[nt][i] = 0.0f; }

    load_chunk(sb, tid, 0, m0, n0, a0, a1, a2, wh, wl, ktot);
    CP_COMMIT();

    const uint32_t aRow = (uint32_t)(wm * 16 + (l & 15));
    const uint32_t aColB = (uint32_t)((l >> 4) * 16);
    const uint32_t bRow = (uint32_t)(wn * 32 + (l & 7) + ((l >> 4) & 1) * 8);
    const uint32_t bColB = (uint32_t)(((l >> 3) & 1) * 16);

    for (int c = 0; c < nch; ++c) {
        const uint32_t stage = sb + (uint32_t)(c & 1) * STAGE_B;
        if (c + 1 < nch) {
            load_chunk(sb + (uint32_t)((c + 1) & 1) * STAGE_B, tid, c + 1, m0, n0,
                       a0, a1, a2, wh, wl, ktot);
            CP_COMMIT();
            CP_WAIT1();
        } else {
            CP_WAIT0();
        }
        __syncthreads();

#pragma unroll
        for (int ks = 0; ks < 4; ++ks) {
            const uint32_t kb = (uint32_t)(ks * 32);   // bytes along k
            uint32_t a[4];
            ldsm4(a, stage + aRow * APITCH + aColB + kb);
            uint32_t b[2][4][2];
#pragma unroll
            for (int split = 0; split < 2; ++split)
#pragma unroll
                for (int ntp = 0; ntp < 2; ++ntp) {
                    uint32_t r4[4];
                    ldsm4(r4, stage + B_OFF + split * B_SPLIT_B +
                              (bRow + ntp * 16) * APITCH + bColB + kb);
                    b[split][ntp * 2][0] = r4[0]; b[split][ntp * 2][1] = r4[1];
                    b[split][ntp * 2 + 1][0] = r4[2]; b[split][ntp * 2 + 1][1] = r4[3];
                }
#pragma unroll
            for (int nt = 0; nt < 4; ++nt) {
                mma16816(acc1[nt], a, b[0][nt]);   // A * W_hi
                mma16816(acc2[nt], a, b[1][nt]);   // A * (W_lo * 1024)
            }
        }
        __syncthreads();
    }

    // ---- epilogue: combine splits, assemble gates, LSTM update ----
    const bool odd = (l & 1) != 0;
#pragma unroll
    for (int nt = 0; nt < 4; ++nt) {
        float cc[4];
#pragma unroll
        for (int i = 0; i < 4; ++i) cc[i] = acc1[nt][i] + acc2[nt][i] * LO_INV;

        float send1 = odd ? cc[0] : cc[2];
        float send2 = odd ? cc[1] : cc[3];
        float r1 = __shfl_xor_sync(0xffffffffu, send1, 1);
        float r2 = __shfl_xor_sync(0xffffffffu, send2, 1);
        float gi, gf, gg, go;
        if (!odd) { gi = cc[0]; gf = cc[1]; gg = r1; go = r2; }
        else      { gi = r1;    gf = r2;    gg = cc[2]; go = cc[3]; }

        const int j = ((n0 + wn * 32 + nt * 8) >> 2) + ((l & 3) >> 1);
        const float4 b4 = *(const float4*)(bias + 4 * j);
        gi += b4.x; gf += b4.y; gg += b4.z; go += b4.w;

        const int bglob = m0 + wm * 16 + (l >> 2) + (odd ? 8 : 0);
        const int ix = bglob * HID + j;
        float cp = cbuf[ix];
        float cn = sigf(gf) * cp + sigf(gi) * tanhf(gg);
        float hn = sigf(go) * tanhf(cn);
        cbuf[ix] = cn;
        hOut[ix] = __float2half(hn);
        if (hOutF != nullptr) hOutF[ix] = hn;
    }
}

// ---------------- FC head (+ next decode-input packing) ----------------
__global__ void fc_head(const float* __restrict__ h1f,
                        const float* __restrict__ fcw, const float* __restrict__ fcb,
                        float* __restrict__ outp, const float* __restrict__ tf) {
    int idx = blockIdx.x * blockDim.x + threadIdx.x;   // 4096 = B*OUT
    int b = idx >> 3, o = idx & 7;
    const float* hr = h1f + b * HID;
    const float* wr = fcw + o * HID;
    float s = fcb[o];
#pragma unroll 8
    for (int j = 0; j < HID; ++j) s += hr[j] * wr[j];
    outp[b * OUT_DIM + o] = s;
    if (tf != nullptr) {
        g_ip[b * 64 + o] = __float2half(s);
#pragma unroll
        for (int m = 0; m < 3; ++m)
            g_ip[b * 64 + 8 + o * 3 + m] = __float2half(tf[b * TF_DIM + o * 3 + m]);
    }
}

// ---------------- host orchestration ----------------
extern "C" void kernel_launch(void* const* d_in, const int* in_sizes, int n_in,
                              void* d_out, int out_size) {
    const float* x     = (const float*)d_in[0];
    const float* ft    = (const float*)d_in[1];
    const float* h0in  = (const float*)d_in[2];
    const float* c0in  = (const float*)d_in[3];
    const float* w_ih0 = (const float*)d_in[4];
    const float* w_hh0 = (const float*)d_in[5];
    const float* b_ih0 = (const float*)d_in[6];
    const float* b_hh0 = (const float*)d_in[7];
    const float* w_ih1 = (const float*)d_in[8];
    const float* w_hh1 = (const float*)d_in[9];
    const float* b_ih1 = (const float*)d_in[10];
    const float* b_hh1 = (const float*)d_in[11];
    const float* fcw   = (const float*)d_in[12];
    const float* fcb   = (const float*)d_in[13];
    float* out = (float*)d_out;

    cudaFuncSetAttribute(lstm_cell_mma, cudaFuncAttributeMaxDynamicSharedMemorySize,
                         SMEM_B);

    __half *w0h, *w0l, *w1h, *w1l, *xp, *ip, *h0p, *h1p;
    float *h1fp, *c0p, *c1p, *b0p, *b1p;
    cudaGetSymbolAddress((void**)&w0h, g_w0h); cudaGetSymbolAddress((void**)&w0l, g_w0l);
    cudaGetSymbolAddress((void**)&w1h, g_w1h); cudaGetSymbolAddress((void**)&w1l, g_w1l);
    cudaGetSymbolAddress((void**)&xp, g_xp);   cudaGetSymbolAddress((void**)&ip, g_ip);
    cudaGetSymbolAddress((void**)&h0p, g_h0);  cudaGetSymbolAddress((void**)&h1p, g_h1);
    cudaGetSymbolAddress((void**)&h1fp, g_h1f);
    cudaGetSymbolAddress((void**)&c0p, g_c0);  cudaGetSymbolAddress((void**)&c1p, g_c1);
    cudaGetSymbolAddress((void**)&b0p, g_b0);  cudaGetSymbolAddress((void**)&b1p, g_b1);

    prep_w0<<<(G4 * KTOT0 + 255) / 256, 256>>>(w_ih0, w_hh0);
    prep_w1<<<(G4 * KTOT1 + 255) / 256, 256>>>(w_ih1, w_hh1);
    prep_bias<<<(G4 + 255) / 256, 256>>>(b_ih0, b_hh0, b_ih1, b_hh1);
    prep_xpad<<<(SEQ * BATCH * 64 + 255) / 256, 256>>>(x);
    prep_ipzero<<<(BATCH * 32 + 255) / 256, 256>>>();
    init_state<<<(BATCH * HID + 255) / 256, 256>>>(h0in, c0in);

    const dim3 grid(16, 8);
    const int SN = BATCH * HID;
    int p = 0;

    // encoder
    for (int t = 0; t < SEQ; ++t) {
        lstm_cell_mma<<<grid, CELL_THREADS, SMEM_B>>>(
            xp + (size_t)t * BATCH * 64,
            h0p + p * SN, nullptr,
            w0h, w0l, KTOT0, NCH0, b0p, c0p,
            h0p + (p ^ 1) * SN, nullptr);
        lstm_cell_mma<<<grid, CELL_THREADS, SMEM_B>>>(
            nullptr,
            h0p + (p ^ 1) * SN, h1p + p * SN,
            w1h, w1l, KTOT1, NCH1, b1p, c1p,
            h1p + (p ^ 1) * SN, h1fp);
        p ^= 1;
    }
    fc_head<<<16, 256>>>(h1fp, fcw, fcb, out, ft);

    // autoregressive decode
    for (int t = 0; t < FUT - 1; ++t) {
        lstm_cell_mma<<<grid, CELL_THREADS, SMEM_B>>>(
            ip,
            h0p + p * SN, nullptr,
            w0h, w0l, KTOT0, NCH0, b0p, c0p,
            h0p + (p ^ 1) * SN, nullptr);
        lstm_cell_mma<<<grid, CELL_THREADS, SMEM_B>>>(
            nullptr,
            h0p + (p ^ 1) * SN, h1p + p * SN,
            w1h, w1l, KTOT1, NCH1, b1p, c1p,
            h1p + (p ^ 1) * SN, h1fp);
        p ^= 1;
        fc_head<<<16, 256>>>(h1fp, fcw, fcb,
                             out + (size_t)(t + 1) * BATCH * OUT_DIM,
                             (t + 1 < FUT - 1) ? (ft + (size_t)(t + 1) * BATCH * TF_DIM)
                                               : nullptr);
    }
}

// round 6
// speedup vs baseline: 3.0587x; 1.4592x over previous
#include <cuda_runtime.h>
#include <cuda_fp16.h>
#include <cstdint>

#define HID 512
#define BATCH 512
#define G4 2048
#define KTOT0 576          // 64 (padded input slab) + 512 (h_prev)
#define KTOT1 1024         // 512 (h0 out) + 512 (h1 prev)
#define NCH0 9
#define NCH1 16
#define SEQ 128
#define FUT 48
#define TF_DIM 24
#define OUT_DIM 8

#define CELL_THREADS 512
#define APITCH 144                    // 64 fp16 (128B) + 16B pad, bank-staggered
#define A_BYTES (64 * APITCH)         // 9216
#define B_OFF A_BYTES
#define B_BYTES (128 * APITCH)        // 18432
#define STAGE_B (B_OFF + B_BYTES)     // 27648
#define SMEM_B (2 * STAGE_B)          // 55296

// ---------------- persistent device buffers ----------------
__device__ __align__(256) __half g_w0h[G4 * KTOT0];
__device__ __align__(256) __half g_w1h[G4 * KTOT1];
__device__ __align__(256) __half g_xp[SEQ * BATCH * 64];
__device__ __align__(256) __half g_ip[BATCH * 64];
__device__ __align__(256) __half g_h0[2][BATCH * HID];
__device__ __align__(256) __half g_h1[2][BATCH * HID];
__device__ __align__(256) float g_h1f[BATCH * HID];   // fp32 h1 for exact FC
__device__ __align__(256) float g_c0[BATCH * HID];
__device__ __align__(256) float g_c1[BATCH * HID];
__device__ __align__(256) float g_b0[G4];
__device__ __align__(256) float g_b1[G4];

// ---------------- PTX helpers (base sm_103-legal only) ----------------
__device__ __forceinline__ uint32_t smem_u32(const void* p) {
    uint32_t a;
    asm("{ .reg .u64 t; cvta.to.shared.u64 t, %1; cvt.u32.u64 %0, t; }" : "=r"(a) : "l"(p));
    return a;
}
__device__ __forceinline__ void cp16(uint32_t dst, const void* src) {
    asm volatile("cp.async.cg.shared.global [%0], [%1], 16;" :: "r"(dst), "l"(src) : "memory");
}
#define CP_COMMIT() asm volatile("cp.async.commit_group;" ::: "memory")
#define CP_WAIT1()  asm volatile("cp.async.wait_group 1;" ::: "memory")
#define CP_WAIT0()  asm volatile("cp.async.wait_group 0;" ::: "memory")

__device__ __forceinline__ void ldsm4(uint32_t* r, uint32_t addr) {
    asm volatile("ldmatrix.sync.aligned.m8n8.x4.shared.b16 {%0,%1,%2,%3}, [%4];"
                 : "=r"(r[0]), "=r"(r[1]), "=r"(r[2]), "=r"(r[3]) : "r"(addr));
}
__device__ __forceinline__ void mma16816(float* c, const uint32_t* a, const uint32_t* b) {
    asm volatile(
        "mma.sync.aligned.m16n8k16.row.col.f32.f16.f16.f32 "
        "{%0,%1,%2,%3}, {%4,%5,%6,%7}, {%8,%9}, {%0,%1,%2,%3};"
        : "+f"(c[0]), "+f"(c[1]), "+f"(c[2]), "+f"(c[3])
        : "r"(a[0]), "r"(a[1]), "r"(a[2]), "r"(a[3]), "r"(b[0]), "r"(b[1]));
}
__device__ __forceinline__ float sigf(float x) { return 1.0f / (1.0f + __expf(-x)); }

// ---------------- prep kernels ----------------
__global__ void prep_w0(const float* __restrict__ wih, const float* __restrict__ whh) {
    int idx = blockIdx.x * blockDim.x + threadIdx.x;
    if (idx >= G4 * KTOT0) return;
    int n = idx / KTOT0, k = idx - n * KTOT0;
    int row = (n & 3) * HID + (n >> 2);
    float v;
    if (k < 64) v = (k < 32) ? wih[row * 32 + k] : 0.0f;
    else        v = whh[row * HID + (k - 64)];
    g_w0h[idx] = __float2half(v);
}
__global__ void prep_w1(const float* __restrict__ wih, const float* __restrict__ whh) {
    int idx = blockIdx.x * blockDim.x + threadIdx.x;
    if (idx >= G4 * KTOT1) return;
    int n = idx >> 10, k = idx & 1023;
    int row = (n & 3) * HID + (n >> 2);
    float v = (k < HID) ? wih[row * HID + k] : whh[row * HID + (k - HID)];
    g_w1h[idx] = __float2half(v);
}
__global__ void prep_bias(const float* __restrict__ bi0, const float* __restrict__ bh0,
                          const float* __restrict__ bi1, const float* __restrict__ bh1) {
    int n = blockIdx.x * blockDim.x + threadIdx.x;
    if (n >= G4) return;
    int row = (n & 3) * HID + (n >> 2);
    g_b0[n] = bi0[row] + bh0[row];
    g_b1[n] = bi1[row] + bh1[row];
}
__global__ void prep_xpad(const float* __restrict__ x) {
    int idx = blockIdx.x * blockDim.x + threadIdx.x;
    if (idx >= SEQ * BATCH * 64) return;
    int k = idx & 63, bt = idx >> 6;
    g_xp[idx] = __float2half((k < 32) ? x[bt * 32 + k] : 0.0f);
}
__global__ void prep_ipzero() {
    int idx = blockIdx.x * blockDim.x + threadIdx.x;
    if (idx >= BATCH * 32) return;
    int b = idx >> 5, i = idx & 31;
    g_ip[b * 64 + 32 + i] = __float2half(0.0f);
}
__global__ void init_state(const float* __restrict__ h0in, const float* __restrict__ c0in) {
    int idx = blockIdx.x * blockDim.x + threadIdx.x;
    if (idx >= BATCH * HID) return;
    int j = idx & (HID - 1);
    g_h0[0][idx] = __float2half(h0in[j]);
    g_h1[0][idx] = __float2half(h0in[HID + j]);
    g_c0[idx] = c0in[j];
    g_c1[idx] = c0in[HID + j];
}

// ---------------- chunk loader ----------------
__device__ __forceinline__ void load_chunk(
    uint32_t stage, int tid, int c, int m0, int n0,
    const __half* a0, const __half* a1, const __half* a2,
    const __half* wh, int ktot)
{
    const char* sA;
    size_t pitchA;
    if (a0 != nullptr && c == 0) {
        sA = (const char*)a0 + (size_t)m0 * 128;
        pitchA = 128;
    } else {
        int s1 = c - (a0 != nullptr ? 1 : 0);
        const __half* src = (s1 < 8) ? a1 : a2;
        if (s1 >= 8) s1 -= 8;
        sA = (const char*)src + (size_t)m0 * 1024 + (size_t)s1 * 128;
        pitchA = 1024;
    }
    const char* sB = (const char*)wh + ((size_t)n0 * ktot + (size_t)c * 64) * 2;
    const size_t pitchB = (size_t)ktot * 2;

    // A: 512 x 16B (one per thread)
    {
        int r = tid >> 3, q = tid & 7;
        cp16(stage + r * APITCH + q * 16, sA + (size_t)r * pitchA + q * 16);
    }
    // B: 1024 x 16B (two per thread, warp-contiguous)
#pragma unroll
    for (int i = 0; i < 2; ++i) {
        int idx = tid + i * CELL_THREADS;
        int r = idx >> 3, q = idx & 7;
        cp16(stage + B_OFF + r * APITCH + q * 16, sB + (size_t)r * pitchB + q * 16);
    }
}

// ---------------- fused LSTM cell (mma.sync fp16) ----------------
__global__ __launch_bounds__(CELL_THREADS, 1)
void lstm_cell_mma(const __half* a0, const __half* a1, const __half* a2,
                   const __half* wh,
                   int ktot, int nch,
                   const float* __restrict__ bias,
                   float* __restrict__ cbuf,
                   __half* __restrict__ hOut,
                   float* __restrict__ hOutF)
{
    extern __shared__ char smem_raw[];
    const uint32_t sb = smem_u32(smem_raw);

    const int tid = threadIdx.x;
    const int l = tid & 31;
    const int w = tid >> 5;
    const int wm = w & 3;          // 0..3 : 16-row slab
    const int wn = w >> 2;         // 0..3 : 32-col slab
    const int n0 = blockIdx.x * 128;
    const int m0 = blockIdx.y * 64;

    float acc[4][4];
#pragma unroll
    for (int nt = 0; nt < 4; ++nt)
#pragma unroll
        for (int i = 0; i < 4; ++i) acc[nt][i] = 0.0f;

    load_chunk(sb, tid, 0, m0, n0, a0, a1, a2, wh, ktot);
    CP_COMMIT();

    const uint32_t aRow = (uint32_t)(wm * 16 + (l & 15));
    const uint32_t aColB = (uint32_t)((l >> 4) * 16);
    const uint32_t bRow = (uint32_t)(wn * 32 + (l & 7) + ((l >> 4) & 1) * 8);
    const uint32_t bColB = (uint32_t)(((l >> 3) & 1) * 16);

    for (int c = 0; c < nch; ++c) {
        const uint32_t stage = sb + (uint32_t)(c & 1) * STAGE_B;
        if (c + 1 < nch) {
            load_chunk(sb + (uint32_t)((c + 1) & 1) * STAGE_B, tid, c + 1, m0, n0,
                       a0, a1, a2, wh, ktot);
            CP_COMMIT();
            CP_WAIT1();
        } else {
            CP_WAIT0();
        }
        __syncthreads();

#pragma unroll
        for (int ks = 0; ks < 4; ++ks) {
            const uint32_t kb = (uint32_t)(ks * 32);   // bytes along k
            uint32_t a[4];
            ldsm4(a, stage + aRow * APITCH + aColB + kb);
            uint32_t b[4][2];
#pragma unroll
            for (int ntp = 0; ntp < 2; ++ntp) {
                uint32_t r4[4];
                ldsm4(r4, stage + B_OFF + (bRow + ntp * 16) * APITCH + bColB + kb);
                b[ntp * 2][0] = r4[0]; b[ntp * 2][1] = r4[1];
                b[ntp * 2 + 1][0] = r4[2]; b[ntp * 2 + 1][1] = r4[3];
            }
#pragma unroll
            for (int nt = 0; nt < 4; ++nt)
                mma16816(acc[nt], a, b[nt]);
        }
        __syncthreads();
    }

    // ---- epilogue: assemble gates via lane-pair exchange, LSTM update ----
    const bool odd = (l & 1) != 0;
#pragma unroll
    for (int nt = 0; nt < 4; ++nt) {
        float* cc = acc[nt];
        float send1 = odd ? cc[0] : cc[2];
        float send2 = odd ? cc[1] : cc[3];
        float r1 = __shfl_xor_sync(0xffffffffu, send1, 1);
        float r2 = __shfl_xor_sync(0xffffffffu, send2, 1);
        float gi, gf, gg, go;
        if (!odd) { gi = cc[0]; gf = cc[1]; gg = r1; go = r2; }
        else      { gi = r1;    gf = r2;    gg = cc[2]; go = cc[3]; }

        const int j = ((n0 + wn * 32 + nt * 8) >> 2) + ((l & 3) >> 1);
        const float4 b4 = *(const float4*)(bias + 4 * j);
        gi += b4.x; gf += b4.y; gg += b4.z; go += b4.w;

        const int bglob = m0 + wm * 16 + (l >> 2) + (odd ? 8 : 0);
        const int ix = bglob * HID + j;
        float cp = cbuf[ix];
        float cn = sigf(gf) * cp + sigf(gi) * tanhf(gg);
        float hn = sigf(go) * tanhf(cn);
        cbuf[ix] = cn;
        hOut[ix] = __float2half(hn);
        if (hOutF != nullptr) hOutF[ix] = hn;
    }
}

// ---------------- FC head (+ next decode-input packing) ----------------
__global__ void fc_head(const float* __restrict__ h1f,
                        const float* __restrict__ fcw, const float* __restrict__ fcb,
                        float* __restrict__ outp, const float* __restrict__ tf) {
    int idx = blockIdx.x * blockDim.x + threadIdx.x;   // 4096 = B*OUT
    int b = idx >> 3, o = idx & 7;
    const float* hr = h1f + b * HID;
    const float* wr = fcw + o * HID;
    float s = fcb[o];
#pragma unroll 8
    for (int j = 0; j < HID; ++j) s += hr[j] * wr[j];
    outp[b * OUT_DIM + o] = s;
    if (tf != nullptr) {
        g_ip[b * 64 + o] = __float2half(s);
#pragma unroll
        for (int m = 0; m < 3; ++m)
            g_ip[b * 64 + 8 + o * 3 + m] = __float2half(tf[b * TF_DIM + o * 3 + m]);
    }
}

// ---------------- host orchestration ----------------
extern "C" void kernel_launch(void* const* d_in, const int* in_sizes, int n_in,
                              void* d_out, int out_size) {
    const float* x     = (const float*)d_in[0];
    const float* ft    = (const float*)d_in[1];
    const float* h0in  = (const float*)d_in[2];
    const float* c0in  = (const float*)d_in[3];
    const float* w_ih0 = (const float*)d_in[4];
    const float* w_hh0 = (const float*)d_in[5];
    const float* b_ih0 = (const float*)d_in[6];
    const float* b_hh0 = (const float*)d_in[7];
    const float* w_ih1 = (const float*)d_in[8];
    const float* w_hh1 = (const float*)d_in[9];
    const float* b_ih1 = (const float*)d_in[10];
    const float* b_hh1 = (const float*)d_in[11];
    const float* fcw   = (const float*)d_in[12];
    const float* fcb   = (const float*)d_in[13];
    float* out = (float*)d_out;

    cudaFuncSetAttribute(lstm_cell_mma, cudaFuncAttributeMaxDynamicSharedMemorySize,
                         SMEM_B);

    __half *w0h, *w1h, *xp, *ip, *h0p, *h1p;
    float *h1fp, *c0p, *c1p, *b0p, *b1p;
    cudaGetSymbolAddress((void**)&w0h, g_w0h);
    cudaGetSymbolAddress((void**)&w1h, g_w1h);
    cudaGetSymbolAddress((void**)&xp, g_xp);   cudaGetSymbolAddress((void**)&ip, g_ip);
    cudaGetSymbolAddress((void**)&h0p, g_h0);  cudaGetSymbolAddress((void**)&h1p, g_h1);
    cudaGetSymbolAddress((void**)&h1fp, g_h1f);
    cudaGetSymbolAddress((void**)&c0p, g_c0);  cudaGetSymbolAddress((void**)&c1p, g_c1);
    cudaGetSymbolAddress((void**)&b0p, g_b0);  cudaGetSymbolAddress((void**)&b1p, g_b1);

    prep_w0<<<(G4 * KTOT0 + 255) / 256, 256>>>(w_ih0, w_hh0);
    prep_w1<<<(G4 * KTOT1 + 255) / 256, 256>>>(w_ih1, w_hh1);
    prep_bias<<<(G4 + 255) / 256, 256>>>(b_ih0, b_hh0, b_ih1, b_hh1);
    prep_xpad<<<(SEQ * BATCH * 64 + 255) / 256, 256>>>(x);
    prep_ipzero<<<(BATCH * 32 + 255) / 256, 256>>>();
    init_state<<<(BATCH * HID + 255) / 256, 256>>>(h0in, c0in);

    const dim3 grid(16, 8);
    const int SN = BATCH * HID;
    int p = 0;

    // encoder
    for (int t = 0; t < SEQ; ++t) {
        lstm_cell_mma<<<grid, CELL_THREADS, SMEM_B>>>(
            xp + (size_t)t * BATCH * 64,
            h0p + p * SN, nullptr,
            w0h, KTOT0, NCH0, b0p, c0p,
            h0p + (p ^ 1) * SN, nullptr);
        lstm_cell_mma<<<grid, CELL_THREADS, SMEM_B>>>(
            nullptr,
            h0p + (p ^ 1) * SN, h1p + p * SN,
            w1h, KTOT1, NCH1, b1p, c1p,
            h1p + (p ^ 1) * SN, h1fp);
        p ^= 1;
    }
    fc_head<<<16, 256>>>(h1fp, fcw, fcb, out, ft);

    // autoregressive decode
    for (int t = 0; t < FUT - 1; ++t) {
        lstm_cell_mma<<<grid, CELL_THREADS, SMEM_B>>>(
            ip,
            h0p + p * SN, nullptr,
            w0h, KTOT0, NCH0, b0p, c0p,
            h0p + (p ^ 1) * SN, nullptr);
        lstm_cell_mma<<<grid, CELL_THREADS, SMEM_B>>>(
            nullptr,
            h0p + (p ^ 1) * SN, h1p + p * SN,
            w1h, KTOT1, NCH1, b1p, c1p,
            h1p + (p ^ 1) * SN, h1fp);
        p ^= 1;
        fc_head<<<16, 256>>>(h1fp, fcw, fcb,
                             out + (size_t)(t + 1) * BATCH * OUT_DIM,
                             (t + 1 < FUT - 1) ? (ft + (size_t)(t + 1) * BATCH * TF_DIM)
                                               : nullptr);
    }
}